// round 1
// baseline (speedup 1.0000x reference)
#include <cuda_runtime.h>
#include <math.h>

#define B_ 8
#define L_ 2048
#define D_ 1024

// Scratch (device globals: allowed by harness rules, no allocation)
__device__ float g_k [(size_t)B_ * L_ * D_];
__device__ float g_qs[(size_t)B_ * L_ * D_];
__device__ float g_qo[(size_t)B_ * L_ * D_];
__device__ float g_v [(size_t)B_ * L_ * D_];
__device__ float g_po[(size_t)B_ * L_ * L_];   // scores_other, then p_self + p_other

// ---------------------------------------------------------------------------
// Tiled SGEMM: C[m,n] = sum_k A[m,k] * B(n,k)   (BT=true,  "NT": B is [N,K])
//              C[m,n] = sum_k A[m,k] * B(k,n)   (BT=false, "NN": B is [K,N])
// 128x128 tile, BK=16, 256 threads, 8x8 per thread. All dims multiples of
// 128/16 for this problem, so no bounds checks.
// ---------------------------------------------------------------------------
template <bool BT>
__global__ __launch_bounds__(256)
void gemm128(const float* __restrict__ A, const float* __restrict__ Bm,
             float* __restrict__ C, int M, int N, int K,
             size_t sA, size_t sB, size_t sC)
{
    __shared__ float As[16][132];
    __shared__ float Bs[16][132];

    const int tid = threadIdx.x;
    const int m0  = blockIdx.y * 128;
    const int n0  = blockIdx.x * 128;

    A  += (size_t)blockIdx.z * sA;
    Bm += (size_t)blockIdx.z * sB;
    C  += (size_t)blockIdx.z * sC;

    float acc[8][8];
    #pragma unroll
    for (int i = 0; i < 8; i++)
        #pragma unroll
        for (int j = 0; j < 8; j++) acc[i][j] = 0.0f;

    const int tx = tid & 15;   // n sub-tile
    const int ty = tid >> 4;   // m sub-tile

    for (int k0 = 0; k0 < K; k0 += 16) {
        // A tile: [128 m][16 k] -> As[k][m] (transposed stage)
        #pragma unroll
        for (int i = 0; i < 2; i++) {
            int idx = tid + i * 256;       // 0..511
            int r   = idx >> 2;            // m row 0..127
            int c   = (idx & 3) << 2;      // k col 0,4,8,12
            float4 v = *(const float4*)(A + (size_t)(m0 + r) * K + k0 + c);
            As[c + 0][r] = v.x; As[c + 1][r] = v.y;
            As[c + 2][r] = v.z; As[c + 3][r] = v.w;
        }
        if (BT) {
            // B tile: [128 n][16 k] -> Bs[k][n]
            #pragma unroll
            for (int i = 0; i < 2; i++) {
                int idx = tid + i * 256;
                int r   = idx >> 2;
                int c   = (idx & 3) << 2;
                float4 v = *(const float4*)(Bm + (size_t)(n0 + r) * K + k0 + c);
                Bs[c + 0][r] = v.x; Bs[c + 1][r] = v.y;
                Bs[c + 2][r] = v.z; Bs[c + 3][r] = v.w;
            }
        } else {
            // B tile: [16 k][128 n] -> Bs[k][n] (direct, fully coalesced)
            #pragma unroll
            for (int i = 0; i < 2; i++) {
                int idx = tid + i * 256;
                int r   = idx >> 5;            // k row 0..15
                int c   = (idx & 31) << 2;     // n col 0..124
                float4 v = *(const float4*)(Bm + (size_t)(k0 + r) * N + n0 + c);
                *(float4*)&Bs[r][c] = v;
            }
        }
        __syncthreads();

        #pragma unroll
        for (int kk = 0; kk < 16; kk++) {
            float ra[8], rb[8];
            *(float4*)&ra[0] = *(const float4*)&As[kk][ty * 8];
            *(float4*)&ra[4] = *(const float4*)&As[kk][ty * 8 + 4];
            *(float4*)&rb[0] = *(const float4*)&Bs[kk][tx * 8];
            *(float4*)&rb[4] = *(const float4*)&Bs[kk][tx * 8 + 4];
            #pragma unroll
            for (int i = 0; i < 8; i++)
                #pragma unroll
                for (int j = 0; j < 8; j++)
                    acc[i][j] = fmaf(ra[i], rb[j], acc[i][j]);
        }
        __syncthreads();
    }

    #pragma unroll
    for (int i = 0; i < 8; i++) {
        float* cr = C + (size_t)(m0 + ty * 8 + i) * N + n0 + tx * 8;
        *(float4*)(cr)     = make_float4(acc[i][0], acc[i][1], acc[i][2], acc[i][3]);
        *(float4*)(cr + 4) = make_float4(acc[i][4], acc[i][5], acc[i][6], acc[i][7]);
    }
}

// ---------------------------------------------------------------------------
// Fused dual softmax: in-place softmax of self-scores (written to d_out
// p_self region) and other-scores; other buffer is overwritten with
// p_self + p_other for the single combined PV GEMM.
// One block = one (b, q) row of length L_=2048. 256 threads x 8 elems.
// ---------------------------------------------------------------------------
__global__ __launch_bounds__(256)
void softmax_combine(const float* __restrict__ mask,
                     float* __restrict__ psf,   // raw self scores -> p_self
                     float* __restrict__ po)    // raw other scores -> p_self+p_other
{
    const int row = blockIdx.x;           // 0 .. B*L-1
    const int b   = row >> 11;            // / L_
    float* ps = psf + (size_t)row * L_;
    float* pc = po  + (size_t)row * L_;
    const float* mk = mask + (size_t)b * L_;

    const int   t     = threadIdx.x;
    const float scale = 0.03125f;         // 1/sqrt(1024)

    float s[8], o[8];
    #pragma unroll
    for (int j = 0; j < 8; j++) {
        int k = t + j * 256;
        float pen = (1.0f - mk[k]) * -100000.0f;
        s[j] = ps[k] * scale + pen;
        o[j] = pc[k] * scale + pen;
    }

    __shared__ float red[2][8];
    const int w  = t >> 5;
    const int ln = t & 31;

    // ---- max reduce (both rows) ----
    float ms = -INFINITY, mo = -INFINITY;
    #pragma unroll
    for (int j = 0; j < 8; j++) { ms = fmaxf(ms, s[j]); mo = fmaxf(mo, o[j]); }
    #pragma unroll
    for (int off = 16; off; off >>= 1) {
        ms = fmaxf(ms, __shfl_xor_sync(0xffffffffu, ms, off));
        mo = fmaxf(mo, __shfl_xor_sync(0xffffffffu, mo, off));
    }
    if (ln == 0) { red[0][w] = ms; red[1][w] = mo; }
    __syncthreads();
    ms = red[0][0]; mo = red[1][0];
    #pragma unroll
    for (int i = 1; i < 8; i++) {
        ms = fmaxf(ms, red[0][i]);
        mo = fmaxf(mo, red[1][i]);
    }
    __syncthreads();

    // ---- exp + sum reduce ----
    float ss = 0.0f, so = 0.0f;
    #pragma unroll
    for (int j = 0; j < 8; j++) {
        s[j] = expf(s[j] - ms); ss += s[j];
        o[j] = expf(o[j] - mo); so += o[j];
    }
    #pragma unroll
    for (int off = 16; off; off >>= 1) {
        ss += __shfl_xor_sync(0xffffffffu, ss, off);
        so += __shfl_xor_sync(0xffffffffu, so, off);
    }
    if (ln == 0) { red[0][w] = ss; red[1][w] = so; }
    __syncthreads();
    ss = 0.0f; so = 0.0f;
    #pragma unroll
    for (int i = 0; i < 8; i++) { ss += red[0][i]; so += red[1][i]; }

    const float rs = 1.0f / ss;
    const float ro = 1.0f / so;
    #pragma unroll
    for (int j = 0; j < 8; j++) {
        int k = t + j * 256;
        float a = s[j] * rs;
        ps[k] = a;                  // p_self (output)
        pc[k] = a + o[j] * ro;      // p_self + p_other (PV operand)
    }
}

// ---------------------------------------------------------------------------
extern "C" void kernel_launch(void* const* d_in, const int* in_sizes, int n_in,
                              void* d_out, int out_size)
{
    const float* x    = (const float*)d_in[0];
    const float* qin  = (const float*)d_in[1];
    const float* vin  = (const float*)d_in[2];
    const float* mask = (const float*)d_in[3];
    const float* Wk   = (const float*)d_in[4];
    const float* Wqs  = (const float*)d_in[5];
    const float* Wqo  = (const float*)d_in[6];
    const float* Wv   = (const float*)d_in[7];

    float *k_, *qs_, *qo_, *v_, *po_;
    cudaGetSymbolAddress((void**)&k_,  g_k);
    cudaGetSymbolAddress((void**)&qs_, g_qs);
    cudaGetSymbolAddress((void**)&qo_, g_qo);
    cudaGetSymbolAddress((void**)&v_,  g_v);
    cudaGetSymbolAddress((void**)&po_, g_po);

    float* out   = (float*)d_out;                    // (B, L, D)
    float* pself = out + (size_t)B_ * L_ * D_;       // (B, L, L)

    dim3 blk(256);

    // 1) Projections: [B*L, D] = X @ W^T  (NT), M=16384, N=1024, K=1024
    dim3 gp(D_ / 128, (B_ * L_) / 128, 1);
    gemm128<true><<<gp, blk>>>(x,   Wk,  k_,  B_ * L_, D_, D_, 0, 0, 0);
    gemm128<true><<<gp, blk>>>(x,   Wqs, qs_, B_ * L_, D_, D_, 0, 0, 0);
    gemm128<true><<<gp, blk>>>(qin, Wqo, qo_, B_ * L_, D_, D_, 0, 0, 0);
    gemm128<true><<<gp, blk>>>(vin, Wv,  v_,  B_ * L_, D_, D_, 0, 0, 0);

    // 2) Scores (batched NT): S[b] = Q[b] @ K[b]^T, M=N=2048, K=1024
    dim3 gs(L_ / 128, L_ / 128, B_);
    gemm128<true><<<gs, blk>>>(qs_, k_, pself, L_, L_, D_,
                               (size_t)L_ * D_, (size_t)L_ * D_, (size_t)L_ * L_);
    gemm128<true><<<gs, blk>>>(qo_, k_, po_,   L_, L_, D_,
                               (size_t)L_ * D_, (size_t)L_ * D_, (size_t)L_ * L_);

    // 3) Dual softmax; po_ becomes p_self + p_other
    softmax_combine<<<B_ * L_, 256>>>(mask, pself, po_);

    // 4) out[b] = (p_self + p_other)[b] @ V[b]  (batched NN), M=2048, N=1024, K=2048
    dim3 gv(D_ / 128, L_ / 128, B_);
    gemm128<false><<<gv, blk>>>(po_, v_, out, L_, D_, L_,
                                (size_t)L_ * L_, (size_t)L_ * D_, (size_t)L_ * D_);
}

// round 3
// speedup vs baseline: 2.3209x; 2.3209x over previous
#include <cuda_runtime.h>
#include <cuda_bf16.h>
#include <math.h>
#include <stdint.h>

#define B_ 8
#define L_ 2048
#define D_ 1024

static const size_t ND = (size_t)B_ * L_ * D_;   // 16,777,216
static const size_t NW = (size_t)D_ * D_;        // 1,048,576

// ---------------- device scratch (globals: no allocation APIs) ----------------
#define GBUF(name, n) __device__ __align__(256) __nv_bfloat16 name[n]
GBUF(g_xh, 16777216);  GBUF(g_xl, 16777216);
GBUF(g_qih, 16777216); GBUF(g_qil, 16777216);
GBUF(g_vih, 16777216); GBUF(g_vil, 16777216);
GBUF(g_wkh, 1048576);  GBUF(g_wkl, 1048576);
GBUF(g_wqsh, 1048576); GBUF(g_wqsl, 1048576);
GBUF(g_wqoh, 1048576); GBUF(g_wqol, 1048576);
GBUF(g_wvh, 1048576);  GBUF(g_wvl, 1048576);
GBUF(g_kh, 16777216);  GBUF(g_kl, 16777216);
GBUF(g_qsh, 16777216); GBUF(g_qsl, 16777216);
GBUF(g_qoh, 16777216); GBUF(g_qol, 16777216);
GBUF(g_vh, 16777216);  GBUF(g_vl, 16777216);
GBUF(g_vth, 16777216); GBUF(g_vtl, 16777216);
GBUF(g_ph, 33554432);  GBUF(g_pl, 33554432);
__device__ __align__(256) float g_po[33554432];

// ---------------- PTX helpers (base sm_103 target: NO tcgen05/TMA) ------------
__device__ __forceinline__ uint32_t smem_u32(const void* p) {
    uint32_t a;
    asm("{ .reg .u64 t; cvta.to.shared.u64 t, %1; cvt.u32.u64 %0, t; }" : "=r"(a) : "l"(p));
    return a;
}

#define CPASYNC(saddr, gptr) \
    asm volatile("cp.async.cg.shared.global [%0], [%1], 16;" \
                 :: "r"(saddr), "l"(gptr) : "memory")
#define CP_COMMIT() asm volatile("cp.async.commit_group;" ::: "memory")
#define CP_WAIT2()  asm volatile("cp.async.wait_group 2;" ::: "memory")

__device__ __forceinline__ void ldmx4(uint32_t* r, uint32_t addr) {
    asm volatile("ldmatrix.sync.aligned.m8n8.x4.shared.b16 {%0,%1,%2,%3}, [%4];"
                 : "=r"(r[0]), "=r"(r[1]), "=r"(r[2]), "=r"(r[3]) : "r"(addr));
}

__device__ __forceinline__ void mma16816(float* c, const uint32_t* a, const uint32_t* b) {
    asm volatile(
        "mma.sync.aligned.m16n8k16.row.col.f32.bf16.bf16.f32 "
        "{%0,%1,%2,%3}, {%4,%5,%6,%7}, {%8,%9}, {%0,%1,%2,%3};"
        : "+f"(c[0]), "+f"(c[1]), "+f"(c[2]), "+f"(c[3])
        : "r"(a[0]), "r"(a[1]), "r"(a[2]), "r"(a[3]), "r"(b[0]), "r"(b[1]));
}

// smem tile: 128 rows x 32 bf16 (64B rows, 4x16B chunks), XOR swizzle on chunk.
// ldmatrix phase check: rows r0..r0+7, fixed chunk -> 8 distinct (addr mod 128).
__device__ __forceinline__ uint32_t swz(int row, int chunk) {
    return (uint32_t)(row * 64 + (((chunk ^ ((row >> 1) & 3)) & 3) << 4));
}

// ---------------- pipelined bf16x3 warp-MMA GEMM (NT) -------------------------
// C[m,n] = sum_k (Ah+Al)[m,k]*(Bh+Bl)[n,k]   (Al*Bl dropped)
// CTA 128x128xK, Kstep=32, 4 stages, 8 warps (2m x 4n), warp tile 64x32.
// EPI=0: fp32 C.  EPI=1: bf16 hi/lo split outputs (Ch, Cl).
#define STG_BYTES 32768
#define GEMM_SMEM (4 * STG_BYTES)

template <int EPI>
__global__ void __launch_bounds__(256, 1)
gemm_ms(const __nv_bfloat16* __restrict__ Ah, const __nv_bfloat16* __restrict__ Al,
        const __nv_bfloat16* __restrict__ Bh, const __nv_bfloat16* __restrict__ Bl,
        float* __restrict__ C, __nv_bfloat16* __restrict__ Ch, __nv_bfloat16* __restrict__ Cl,
        int K, int ldc, size_t sA, size_t sB, size_t sC)
{
    extern __shared__ __align__(128) char smem[];
    const uint32_t smemU = smem_u32(smem);

    const int tid  = threadIdx.x;
    const int wid  = tid >> 5;
    const int lane = tid & 31;
    const int m0 = blockIdx.y * 128, n0 = blockIdx.x * 128;
    const size_t z = blockIdx.z;

    Ah += z * sA; Al += z * sA;
    Bh += z * sB; Bl += z * sB;
    if (EPI == 0) { C += z * sC; } else { Ch += z * sC; Cl += z * sC; }

    // load mapping: each thread owns one row-half (2 chunks) per operand
    const int lrow = tid >> 1;            // 0..127
    const int lc0  = (tid & 1) * 2;       // chunk base 0 or 2
    const __nv_bfloat16* gAh = Ah + (size_t)(m0 + lrow) * K;
    const __nv_bfloat16* gAl = Al + (size_t)(m0 + lrow) * K;
    const __nv_bfloat16* gBh = Bh + (size_t)(n0 + lrow) * K;
    const __nv_bfloat16* gBl = Bl + (size_t)(n0 + lrow) * K;

    const int wm64 = (wid & 1) * 64;
    const int wn32 = (wid >> 1) * 32;

    float acc[64];
    #pragma unroll
    for (int i = 0; i < 64; i++) acc[i] = 0.0f;

    const int KT = K >> 5;   // k-steps of 32

    #define ISSUE_STAGE(KF, SLOT) do {                                   \
        uint32_t _sb = smemU + (uint32_t)(SLOT) * STG_BYTES;             \
        size_t _ko = (size_t)(KF) * 32;                                  \
        _Pragma("unroll")                                                \
        for (int _j = 0; _j < 2; _j++) {                                 \
            int _ch = lc0 + _j;                                          \
            uint32_t _so = _sb + swz(lrow, _ch);                         \
            size_t _go = _ko + (size_t)_ch * 8;                          \
            CPASYNC(_so,          gAh + _go);                            \
            CPASYNC(_so +  8192u, gAl + _go);                            \
            CPASYNC(_so + 16384u, gBh + _go);                            \
            CPASYNC(_so + 24576u, gBl + _go);                            \
        }                                                                \
    } while (0)

    // prologue: fill 3 stages
    ISSUE_STAGE(0, 0); CP_COMMIT();
    ISSUE_STAGE(1, 1); CP_COMMIT();
    ISSUE_STAGE(2, 2); CP_COMMIT();

    for (int kt = 0; kt < KT; kt++) {
        CP_WAIT2();
        __syncthreads();

        int kf = kt + 3;
        if (kf < KT) ISSUE_STAGE(kf, kf & 3);
        CP_COMMIT();

        const uint32_t sb = smemU + (uint32_t)(kt & 3) * STG_BYTES;
        #pragma unroll
        for (int k16 = 0; k16 < 2; k16++) {
            uint32_t bh[8], bl[8];
            #pragma unroll
            for (int tp = 0; tp < 2; tp++) {
                int brow = wn32 + tp * 16 + (lane & 7) + ((lane >> 4) << 3);
                int bch  = k16 * 2 + ((lane >> 3) & 1);
                uint32_t off = swz(brow, bch);
                ldmx4(&bh[tp * 4], sb + 16384u + off);
                ldmx4(&bl[tp * 4], sb + 24576u + off);
            }
            #pragma unroll
            for (int tm = 0; tm < 4; tm++) {
                int arow = wm64 + tm * 16 + (lane & 15);
                int ach  = k16 * 2 + (lane >> 4);
                uint32_t off = swz(arow, ach);
                uint32_t ah[4], al[4];
                ldmx4(ah, sb + off);
                ldmx4(al, sb + 8192u + off);
                #pragma unroll
                for (int tn = 0; tn < 4; tn++) {
                    float* c = acc + (tm * 4 + tn) * 4;
                    mma16816(c, ah, &bh[tn * 2]);
                    mma16816(c, al, &bh[tn * 2]);
                    mma16816(c, ah, &bl[tn * 2]);
                }
            }
        }
    }
    #undef ISSUE_STAGE

    // epilogue: direct stores from mma accumulator layout
    #pragma unroll
    for (int tm = 0; tm < 4; tm++) {
        #pragma unroll
        for (int tn = 0; tn < 4; tn++) {
            const float* c = acc + (tm * 4 + tn) * 4;
            int row0 = m0 + wm64 + tm * 16 + (lane >> 2);
            int col  = n0 + wn32 + tn * 8 + (lane & 3) * 2;
            size_t i0 = (size_t)row0 * ldc + col;
            size_t i1 = i0 + (size_t)8 * ldc;
            if (EPI == 0) {
                *(float2*)(C + i0) = make_float2(c[0], c[1]);
                *(float2*)(C + i1) = make_float2(c[2], c[3]);
            } else {
                #pragma unroll
                for (int p = 0; p < 2; p++) {
                    size_t ix = p ? i1 : i0;
                    float v0 = c[p * 2], v1 = c[p * 2 + 1];
                    __nv_bfloat16 h0 = __float2bfloat16(v0);
                    __nv_bfloat16 h1 = __float2bfloat16(v1);
                    __nv_bfloat16 l0 = __float2bfloat16(v0 - __bfloat162float(h0));
                    __nv_bfloat16 l1 = __float2bfloat16(v1 - __bfloat162float(h1));
                    uint32_t hp = (uint32_t)__bfloat16_as_ushort(h0) |
                                  ((uint32_t)__bfloat16_as_ushort(h1) << 16);
                    uint32_t lp = (uint32_t)__bfloat16_as_ushort(l0) |
                                  ((uint32_t)__bfloat16_as_ushort(l1) << 16);
                    *(uint32_t*)(Ch + ix) = hp;
                    *(uint32_t*)(Cl + ix) = lp;
                }
            }
        }
    }
}

// ---------------- fp32 -> bf16 hi/lo split (vectorized) ------------------------
__global__ void __launch_bounds__(256)
split_k(const float4* __restrict__ in, uint2* __restrict__ hi, uint2* __restrict__ lo, int n4)
{
    int i = blockIdx.x * 256 + threadIdx.x;
    if (i >= n4) return;
    float4 v = in[i];
    __nv_bfloat16 h0 = __float2bfloat16(v.x), h1 = __float2bfloat16(v.y);
    __nv_bfloat16 h2 = __float2bfloat16(v.z), h3 = __float2bfloat16(v.w);
    __nv_bfloat16 l0 = __float2bfloat16(v.x - __bfloat162float(h0));
    __nv_bfloat16 l1 = __float2bfloat16(v.y - __bfloat162float(h1));
    __nv_bfloat16 l2 = __float2bfloat16(v.z - __bfloat162float(h2));
    __nv_bfloat16 l3 = __float2bfloat16(v.w - __bfloat162float(h3));
    uint2 H, L;
    H.x = (uint32_t)__bfloat16_as_ushort(h0) | ((uint32_t)__bfloat16_as_ushort(h1) << 16);
    H.y = (uint32_t)__bfloat16_as_ushort(h2) | ((uint32_t)__bfloat16_as_ushort(h3) << 16);
    L.x = (uint32_t)__bfloat16_as_ushort(l0) | ((uint32_t)__bfloat16_as_ushort(l1) << 16);
    L.y = (uint32_t)__bfloat16_as_ushort(l2) | ((uint32_t)__bfloat16_as_ushort(l3) << 16);
    hi[i] = H; lo[i] = L;
}

// ---------------- per-batch bf16 transpose: [B,L,D] -> [B,D,L] -----------------
__global__ void __launch_bounds__(256)
transp_k(const __nv_bfloat16* __restrict__ src, __nv_bfloat16* __restrict__ dst)
{
    __shared__ __nv_bfloat16 t[32][33];
    const int b = blockIdx.z;
    const int d0 = blockIdx.x * 32, l0 = blockIdx.y * 32;
    const int tx = threadIdx.x, ty = threadIdx.y;  // 32 x 8
    const __nv_bfloat16* s = src + (size_t)b * L_ * D_;
    __nv_bfloat16* o = dst + (size_t)b * D_ * L_;
    #pragma unroll
    for (int j = 0; j < 4; j++)
        t[ty + j * 8][tx] = s[(size_t)(l0 + ty + j * 8) * D_ + d0 + tx];
    __syncthreads();
    #pragma unroll
    for (int j = 0; j < 4; j++)
        o[(size_t)(d0 + ty + j * 8) * L_ + l0 + tx] = t[tx][ty + j * 8];
}

// ---------------- dual softmax + combined-p bf16 split --------------------------
__global__ void __launch_bounds__(256)
softmax_combine(const float* __restrict__ mask,
                float* __restrict__ psf,          // raw self scores -> p_self (fp32 out)
                const float* __restrict__ po,     // raw other scores
                __nv_bfloat16* __restrict__ ph,   // (p_self+p_other) hi
                __nv_bfloat16* __restrict__ pl)   // (p_self+p_other) lo
{
    const int row = blockIdx.x;
    const int b   = row >> 11;
    float* ps = psf + (size_t)row * L_;
    const float* pc = po + (size_t)row * L_;
    __nv_bfloat16* phr = ph + (size_t)row * L_;
    __nv_bfloat16* plr = pl + (size_t)row * L_;
    const float* mk = mask + (size_t)b * L_;

    const int t = threadIdx.x;
    const float scale = 0.03125f;

    float s[8], o[8];
    #pragma unroll
    for (int j = 0; j < 8; j++) {
        int k = t + j * 256;
        float pen = (1.0f - mk[k]) * -100000.0f;
        s[j] = ps[k] * scale + pen;
        o[j] = pc[k] * scale + pen;
    }

    __shared__ float red[2][8];
    const int w = t >> 5, ln = t & 31;

    float ms = -INFINITY, mo = -INFINITY;
    #pragma unroll
    for (int j = 0; j < 8; j++) { ms = fmaxf(ms, s[j]); mo = fmaxf(mo, o[j]); }
    #pragma unroll
    for (int off = 16; off; off >>= 1) {
        ms = fmaxf(ms, __shfl_xor_sync(0xffffffffu, ms, off));
        mo = fmaxf(mo, __shfl_xor_sync(0xffffffffu, mo, off));
    }
    if (ln == 0) { red[0][w] = ms; red[1][w] = mo; }
    __syncthreads();
    ms = red[0][0]; mo = red[1][0];
    #pragma unroll
    for (int i = 1; i < 8; i++) { ms = fmaxf(ms, red[0][i]); mo = fmaxf(mo, red[1][i]); }
    __syncthreads();

    float ss = 0.0f, so = 0.0f;
    #pragma unroll
    for (int j = 0; j < 8; j++) {
        s[j] = expf(s[j] - ms); ss += s[j];
        o[j] = expf(o[j] - mo); so += o[j];
    }
    #pragma unroll
    for (int off = 16; off; off >>= 1) {
        ss += __shfl_xor_sync(0xffffffffu, ss, off);
        so += __shfl_xor_sync(0xffffffffu, so, off);
    }
    if (ln == 0) { red[0][w] = ss; red[1][w] = so; }
    __syncthreads();
    ss = 0.0f; so = 0.0f;
    #pragma unroll
    for (int i = 0; i < 8; i++) { ss += red[0][i]; so += red[1][i]; }

    const float rs = 1.0f / ss, ro = 1.0f / so;
    #pragma unroll
    for (int j = 0; j < 8; j++) {
        int k = t + j * 256;
        float a = s[j] * rs;
        ps[k] = a;
        float comb = a + o[j] * ro;
        __nv_bfloat16 h = __float2bfloat16(comb);
        phr[k] = h;
        plr[k] = __float2bfloat16(comb - __bfloat162float(h));
    }
}

// ---------------- host ----------------------------------------------------------
extern "C" void kernel_launch(void* const* d_in, const int* in_sizes, int n_in,
                              void* d_out, int out_size)
{
    const float* x    = (const float*)d_in[0];
    const float* qin  = (const float*)d_in[1];
    const float* vin  = (const float*)d_in[2];
    const float* mask = (const float*)d_in[3];
    const float* Wk   = (const float*)d_in[4];
    const float* Wqs  = (const float*)d_in[5];
    const float* Wqo  = (const float*)d_in[6];
    const float* Wv   = (const float*)d_in[7];

    #define SYMP(T, p, s) T* p; { void* _t; cudaGetSymbolAddress(&_t, s); p = (T*)_t; }
    SYMP(__nv_bfloat16, xh,  g_xh)  SYMP(__nv_bfloat16, xl,  g_xl)
    SYMP(__nv_bfloat16, qih, g_qih) SYMP(__nv_bfloat16, qil, g_qil)
    SYMP(__nv_bfloat16, vih, g_vih) SYMP(__nv_bfloat16, vil, g_vil)
    SYMP(__nv_bfloat16, wkh, g_wkh) SYMP(__nv_bfloat16, wkl, g_wkl)
    SYMP(__nv_bfloat16, wqsh,g_wqsh)SYMP(__nv_bfloat16, wqsl,g_wqsl)
    SYMP(__nv_bfloat16, wqoh,g_wqoh)SYMP(__nv_bfloat16, wqol,g_wqol)
    SYMP(__nv_bfloat16, wvh, g_wvh) SYMP(__nv_bfloat16, wvl, g_wvl)
    SYMP(__nv_bfloat16, kh,  g_kh)  SYMP(__nv_bfloat16, kl,  g_kl)
    SYMP(__nv_bfloat16, qsh, g_qsh) SYMP(__nv_bfloat16, qsl, g_qsl)
    SYMP(__nv_bfloat16, qoh, g_qoh) SYMP(__nv_bfloat16, qol, g_qol)
    SYMP(__nv_bfloat16, vh,  g_vh)  SYMP(__nv_bfloat16, vl,  g_vl)
    SYMP(__nv_bfloat16, vth, g_vth) SYMP(__nv_bfloat16, vtl, g_vtl)
    SYMP(__nv_bfloat16, ph,  g_ph)  SYMP(__nv_bfloat16, pl,  g_pl)
    SYMP(float, po, g_po)

    float* out   = (float*)d_out;
    float* pself = out + ND;

    cudaFuncSetAttribute(gemm_ms<0>, cudaFuncAttributeMaxDynamicSharedMemorySize, GEMM_SMEM);
    cudaFuncSetAttribute(gemm_ms<1>, cudaFuncAttributeMaxDynamicSharedMemorySize, GEMM_SMEM);

    // 1) split inputs to bf16 hi/lo
    const int ND4 = (int)(ND / 4), NW4 = (int)(NW / 4);
    split_k<<<(ND4 + 255) / 256, 256>>>((const float4*)x,   (uint2*)xh,  (uint2*)xl,  ND4);
    split_k<<<(ND4 + 255) / 256, 256>>>((const float4*)qin, (uint2*)qih, (uint2*)qil, ND4);
    split_k<<<(ND4 + 255) / 256, 256>>>((const float4*)vin, (uint2*)vih, (uint2*)vil, ND4);
    split_k<<<(NW4 + 255) / 256, 256>>>((const float4*)Wk,  (uint2*)wkh, (uint2*)wkl, NW4);
    split_k<<<(NW4 + 255) / 256, 256>>>((const float4*)Wqs, (uint2*)wqsh,(uint2*)wqsl,NW4);
    split_k<<<(NW4 + 255) / 256, 256>>>((const float4*)Wqo, (uint2*)wqoh,(uint2*)wqol,NW4);
    split_k<<<(NW4 + 255) / 256, 256>>>((const float4*)Wv,  (uint2*)wvh, (uint2*)wvl, NW4);

    // 2) projections (NT, M=16384, N=1024, K=1024) -> bf16 split outputs
    dim3 gp(8, 128, 1), blk(256);
    gemm_ms<1><<<gp, blk, GEMM_SMEM>>>(xh,  xl,  wkh,  wkl,  nullptr, kh,  kl,  1024, 1024, 0, 0, 0);
    gemm_ms<1><<<gp, blk, GEMM_SMEM>>>(xh,  xl,  wqsh, wqsl, nullptr, qsh, qsl, 1024, 1024, 0, 0, 0);
    gemm_ms<1><<<gp, blk, GEMM_SMEM>>>(qih, qil, wqoh, wqol, nullptr, qoh, qol, 1024, 1024, 0, 0, 0);
    gemm_ms<1><<<gp, blk, GEMM_SMEM>>>(vih, vil, wvh,  wvl,  nullptr, vh,  vl,  1024, 1024, 0, 0, 0);

    // 3) transpose V per batch: [B,L,D] -> [B,D,L]
    dim3 gt(32, 64, 8), bt(32, 8);
    transp_k<<<gt, bt>>>(vh, vth);
    transp_k<<<gt, bt>>>(vl, vtl);

    // 4) scores (batched NT, M=N=2048, K=1024) -> fp32
    dim3 gs(16, 16, 8);
    gemm_ms<0><<<gs, blk, GEMM_SMEM>>>(qsh, qsl, kh, kl, pself, nullptr, nullptr,
                                       1024, 2048, (size_t)L_ * D_, (size_t)L_ * D_, (size_t)L_ * L_);
    gemm_ms<0><<<gs, blk, GEMM_SMEM>>>(qoh, qol, kh, kl, po, nullptr, nullptr,
                                       1024, 2048, (size_t)L_ * D_, (size_t)L_ * D_, (size_t)L_ * L_);

    // 5) dual softmax; emits p_self fp32 + combined-p bf16 split
    softmax_combine<<<B_ * L_, 256>>>(mask, pself, po, ph, pl);

    // 6) out = (p_self + p_other) @ V  (batched NT vs V^T, M=2048, N=1024, K=2048)
    dim3 gv(8, 16, 8);
    gemm_ms<0><<<gv, blk, GEMM_SMEM>>>(ph, pl, vth, vtl, out, nullptr, nullptr,
                                       2048, 1024, (size_t)L_ * L_, (size_t)D_ * L_, (size_t)L_ * D_);
}

// round 4
// speedup vs baseline: 2.7752x; 1.1958x over previous
#include <cuda_runtime.h>
#include <cuda_bf16.h>
#include <math.h>
#include <stdint.h>

#define B_ 8
#define L_ 2048
#define D_ 1024

static const size_t ND = (size_t)B_ * L_ * D_;   // 16,777,216
static const size_t NW = (size_t)D_ * D_;        // 1,048,576

// ---------------- device scratch (globals: no allocation APIs) ----------------
#define GBUF(name, n) __device__ __align__(256) __nv_bfloat16 name[n]
GBUF(g_xh, 16777216);  GBUF(g_xl, 16777216);
GBUF(g_qih, 16777216); GBUF(g_qil, 16777216);
GBUF(g_vih, 16777216); GBUF(g_vil, 16777216);
GBUF(g_wkh, 1048576);  GBUF(g_wkl, 1048576);
GBUF(g_wqsh, 1048576); GBUF(g_wqsl, 1048576);
GBUF(g_wqoh, 1048576); GBUF(g_wqol, 1048576);
GBUF(g_wvh, 1048576);  GBUF(g_wvl, 1048576);
GBUF(g_kh, 16777216);  GBUF(g_kl, 16777216);
GBUF(g_qsh, 16777216); GBUF(g_qsl, 16777216);
GBUF(g_qoh, 16777216); GBUF(g_qol, 16777216);
GBUF(g_vh, 16777216);  GBUF(g_vl, 16777216);
GBUF(g_vth, 16777216); GBUF(g_vtl, 16777216);
GBUF(g_ph, 33554432);  GBUF(g_pl, 33554432);
__device__ __align__(256) float g_po[33554432];

// ---------------- PTX helpers (base sm_103 target: NO tcgen05/TMA) ------------
__device__ __forceinline__ uint32_t smem_u32(const void* p) {
    uint32_t a;
    asm("{ .reg .u64 t; cvta.to.shared.u64 t, %1; cvt.u32.u64 %0, t; }" : "=r"(a) : "l"(p));
    return a;
}

#define CPASYNC(saddr, gptr) \
    asm volatile("cp.async.cg.shared.global [%0], [%1], 16;" \
                 :: "r"(saddr), "l"(gptr) : "memory")
#define CP_COMMIT() asm volatile("cp.async.commit_group;" ::: "memory")
#define CP_WAIT2()  asm volatile("cp.async.wait_group 2;" ::: "memory")

__device__ __forceinline__ void ldmx4(uint32_t* r, uint32_t addr) {
    asm volatile("ldmatrix.sync.aligned.m8n8.x4.shared.b16 {%0,%1,%2,%3}, [%4];"
                 : "=r"(r[0]), "=r"(r[1]), "=r"(r[2]), "=r"(r[3]) : "r"(addr));
}

__device__ __forceinline__ void mma16816(float* c, const uint32_t* a, const uint32_t* b) {
    asm volatile(
        "mma.sync.aligned.m16n8k16.row.col.f32.bf16.bf16.f32 "
        "{%0,%1,%2,%3}, {%4,%5,%6,%7}, {%8,%9}, {%0,%1,%2,%3};"
        : "+f"(c[0]), "+f"(c[1]), "+f"(c[2]), "+f"(c[3])
        : "r"(a[0]), "r"(a[1]), "r"(a[2]), "r"(a[3]), "r"(b[0]), "r"(b[1]));
}

// smem tile rows of 32 bf16 (64B, 4x16B chunks), XOR swizzle on chunk.
__device__ __forceinline__ uint32_t swz(int row, int chunk) {
    return (uint32_t)(row * 64 + (((chunk ^ ((row >> 1) & 3)) & 3) << 4));
}

// ---------------- pipelined bf16x3 warp-MMA GEMM (NT) -------------------------
// C[m,n] = sum_k (Ah+Al)[m,k]*(Bh+Bl)[n,k]   (Al*Bl dropped)
// CTA 256x128xK, Kstep=32, 4 stages, 8 warps (4m x 2n), warp tile 64x64.
// Stage layout: Ah[256x32]@0 (16KB), Al@16K, Bh[128x32]@32K (8KB), Bl@40K.
#define STG_BYTES 49152
#define GEMM_SMEM (4 * STG_BYTES)   // 192 KB

template <int EPI>
__global__ void __launch_bounds__(256, 1)
gemm_ms(const __nv_bfloat16* __restrict__ Ah, const __nv_bfloat16* __restrict__ Al,
        const __nv_bfloat16* __restrict__ Bh, const __nv_bfloat16* __restrict__ Bl,
        float* __restrict__ C, __nv_bfloat16* __restrict__ Ch, __nv_bfloat16* __restrict__ Cl,
        int K, int ldc, size_t sA, size_t sB, size_t sC)
{
    extern __shared__ __align__(128) char smem[];
    const uint32_t smemU = smem_u32(smem);

    const int tid  = threadIdx.x;
    const int wid  = tid >> 5;
    const int lane = tid & 31;
    const int m0 = blockIdx.y * 256, n0 = blockIdx.x * 128;
    const size_t z = blockIdx.z;

    Ah += z * sA; Al += z * sA;
    Bh += z * sB; Bl += z * sB;
    if (EPI == 0) { C += z * sC; } else { Ch += z * sC; Cl += z * sC; }

    const int wm64 = (wid & 3) * 64;
    const int wn64 = (wid >> 2) * 64;

    float acc[128];
    #pragma unroll
    for (int i = 0; i < 128; i++) acc[i] = 0.0f;

    const int KT = K >> 5;   // k-steps of 32

    // load mapping: A tensors 1024 chunks each (4/thread), B tensors 512 (2/thread)
    #define ISSUE_STAGE(KF, SLOT) do {                                        \
        uint32_t _sb = smemU + (uint32_t)(SLOT) * STG_BYTES;                  \
        size_t _ko = (size_t)(KF) * 32;                                       \
        _Pragma("unroll")                                                     \
        for (int _i = 0; _i < 4; _i++) {                                      \
            int _c = tid + _i * 256;                                          \
            int _r = _c >> 2, _ch = _c & 3;                                   \
            uint32_t _so = swz(_r, _ch);                                      \
            size_t _go = (size_t)(m0 + _r) * K + _ko + (size_t)_ch * 8;       \
            CPASYNC(_sb + _so,          Ah + _go);                            \
            CPASYNC(_sb + 16384u + _so, Al + _go);                            \
        }                                                                     \
        _Pragma("unroll")                                                     \
        for (int _i = 0; _i < 2; _i++) {                                      \
            int _c = tid + _i * 256;                                          \
            int _r = _c >> 2, _ch = _c & 3;                                   \
            uint32_t _so = swz(_r, _ch);                                      \
            size_t _go = (size_t)(n0 + _r) * K + _ko + (size_t)_ch * 8;       \
            CPASYNC(_sb + 32768u + _so, Bh + _go);                            \
            CPASYNC(_sb + 40960u + _so, Bl + _go);                            \
        }                                                                     \
    } while (0)

    // prologue: fill 3 stages
    ISSUE_STAGE(0, 0); CP_COMMIT();
    ISSUE_STAGE(1, 1); CP_COMMIT();
    ISSUE_STAGE(2, 2); CP_COMMIT();

    for (int kt = 0; kt < KT; kt++) {
        CP_WAIT2();
        __syncthreads();

        int kf = kt + 3;
        if (kf < KT) ISSUE_STAGE(kf, kf & 3);   // slot (kt-1)&3: freed by the sync above
        CP_COMMIT();

        const uint32_t sb = smemU + (uint32_t)(kt & 3) * STG_BYTES;
        #pragma unroll
        for (int k16 = 0; k16 < 2; k16++) {
            uint32_t bh[16], bl[16];
            #pragma unroll
            for (int tp = 0; tp < 4; tp++) {
                int brow = wn64 + tp * 16 + (lane & 7) + ((lane >> 4) << 3);
                int bch  = k16 * 2 + ((lane >> 3) & 1);
                uint32_t off = swz(brow, bch);
                ldmx4(&bh[tp * 4], sb + 32768u + off);
                ldmx4(&bl[tp * 4], sb + 40960u + off);
            }
            #pragma unroll
            for (int tm = 0; tm < 4; tm++) {
                int arow = wm64 + tm * 16 + (lane & 15);
                int ach  = k16 * 2 + (lane >> 4);
                uint32_t off = swz(arow, ach);
                uint32_t ah[4], al[4];
                ldmx4(ah, sb + off);
                ldmx4(al, sb + 16384u + off);
                #pragma unroll
                for (int tn = 0; tn < 8; tn++) {
                    float* c = acc + (tm * 8 + tn) * 4;
                    mma16816(c, ah, &bh[tn * 2]);
                    mma16816(c, al, &bh[tn * 2]);
                    mma16816(c, ah, &bl[tn * 2]);
                }
            }
        }
    }
    #undef ISSUE_STAGE

    // epilogue: direct stores from mma accumulator layout
    #pragma unroll
    for (int tm = 0; tm < 4; tm++) {
        #pragma unroll
        for (int tn = 0; tn < 8; tn++) {
            const float* c = acc + (tm * 8 + tn) * 4;
            int row0 = m0 + wm64 + tm * 16 + (lane >> 2);
            int col  = n0 + wn64 + tn * 8 + (lane & 3) * 2;
            size_t i0 = (size_t)row0 * ldc + col;
            size_t i1 = i0 + (size_t)8 * ldc;
            if (EPI == 0) {
                *(float2*)(C + i0) = make_float2(c[0], c[1]);
                *(float2*)(C + i1) = make_float2(c[2], c[3]);
            } else {
                #pragma unroll
                for (int p = 0; p < 2; p++) {
                    size_t ix = p ? i1 : i0;
                    float v0 = c[p * 2], v1 = c[p * 2 + 1];
                    __nv_bfloat16 h0 = __float2bfloat16(v0);
                    __nv_bfloat16 h1 = __float2bfloat16(v1);
                    __nv_bfloat16 l0 = __float2bfloat16(v0 - __bfloat162float(h0));
                    __nv_bfloat16 l1 = __float2bfloat16(v1 - __bfloat162float(h1));
                    uint32_t hp = (uint32_t)__bfloat16_as_ushort(h0) |
                                  ((uint32_t)__bfloat16_as_ushort(h1) << 16);
                    uint32_t lp = (uint32_t)__bfloat16_as_ushort(l0) |
                                  ((uint32_t)__bfloat16_as_ushort(l1) << 16);
                    *(uint32_t*)(Ch + ix) = hp;
                    *(uint32_t*)(Cl + ix) = lp;
                }
            }
        }
    }
}

// ---------------- fp32 -> bf16 hi/lo split (vectorized) ------------------------
__global__ void __launch_bounds__(256)
split_k(const float4* __restrict__ in, uint2* __restrict__ hi, uint2* __restrict__ lo, int n4)
{
    int i = blockIdx.x * 256 + threadIdx.x;
    if (i >= n4) return;
    float4 v = in[i];
    __nv_bfloat16 h0 = __float2bfloat16(v.x), h1 = __float2bfloat16(v.y);
    __nv_bfloat16 h2 = __float2bfloat16(v.z), h3 = __float2bfloat16(v.w);
    __nv_bfloat16 l0 = __float2bfloat16(v.x - __bfloat162float(h0));
    __nv_bfloat16 l1 = __float2bfloat16(v.y - __bfloat162float(h1));
    __nv_bfloat16 l2 = __float2bfloat16(v.z - __bfloat162float(h2));
    __nv_bfloat16 l3 = __float2bfloat16(v.w - __bfloat162float(h3));
    uint2 H, L;
    H.x = (uint32_t)__bfloat16_as_ushort(h0) | ((uint32_t)__bfloat16_as_ushort(h1) << 16);
    H.y = (uint32_t)__bfloat16_as_ushort(h2) | ((uint32_t)__bfloat16_as_ushort(h3) << 16);
    L.x = (uint32_t)__bfloat16_as_ushort(l0) | ((uint32_t)__bfloat16_as_ushort(l1) << 16);
    L.y = (uint32_t)__bfloat16_as_ushort(l2) | ((uint32_t)__bfloat16_as_ushort(l3) << 16);
    hi[i] = H; lo[i] = L;
}

// ---------------- per-batch bf16 transpose: [B,L,D] -> [B,D,L] -----------------
__global__ void __launch_bounds__(256)
transp_k(const __nv_bfloat16* __restrict__ src, __nv_bfloat16* __restrict__ dst)
{
    __shared__ __nv_bfloat16 t[32][33];
    const int b = blockIdx.z;
    const int d0 = blockIdx.x * 32, l0 = blockIdx.y * 32;
    const int tx = threadIdx.x, ty = threadIdx.y;  // 32 x 8
    const __nv_bfloat16* s = src + (size_t)b * L_ * D_;
    __nv_bfloat16* o = dst + (size_t)b * D_ * L_;
    #pragma unroll
    for (int j = 0; j < 4; j++)
        t[ty + j * 8][tx] = s[(size_t)(l0 + ty + j * 8) * D_ + d0 + tx];
    __syncthreads();
    #pragma unroll
    for (int j = 0; j < 4; j++)
        o[(size_t)(d0 + ty + j * 8) * L_ + l0 + tx] = t[tx][ty + j * 8];
}

// ---------------- dual softmax + combined-p bf16 split --------------------------
__global__ void __launch_bounds__(256)
softmax_combine(const float* __restrict__ mask,
                float* __restrict__ psf,          // raw self scores -> p_self (fp32 out)
                const float* __restrict__ po,     // raw other scores
                __nv_bfloat16* __restrict__ ph,   // (p_self+p_other) hi
                __nv_bfloat16* __restrict__ pl)   // (p_self+p_other) lo
{
    const int row = blockIdx.x;
    const int b   = row >> 11;
    float* ps = psf + (size_t)row * L_;
    const float* pc = po + (size_t)row * L_;
    __nv_bfloat16* phr = ph + (size_t)row * L_;
    __nv_bfloat16* plr = pl + (size_t)row * L_;
    const float* mk = mask + (size_t)b * L_;

    const int t = threadIdx.x;
    const float scale = 0.03125f;

    float s[8], o[8];
    #pragma unroll
    for (int j = 0; j < 8; j++) {
        int k = t + j * 256;
        float pen = (1.0f - mk[k]) * -100000.0f;
        s[j] = ps[k] * scale + pen;
        o[j] = pc[k] * scale + pen;
    }

    __shared__ float red[2][8];
    const int w = t >> 5, ln = t & 31;

    float ms = -INFINITY, mo = -INFINITY;
    #pragma unroll
    for (int j = 0; j < 8; j++) { ms = fmaxf(ms, s[j]); mo = fmaxf(mo, o[j]); }
    #pragma unroll
    for (int off = 16; off; off >>= 1) {
        ms = fmaxf(ms, __shfl_xor_sync(0xffffffffu, ms, off));
        mo = fmaxf(mo, __shfl_xor_sync(0xffffffffu, mo, off));
    }
    if (ln == 0) { red[0][w] = ms; red[1][w] = mo; }
    __syncthreads();
    ms = red[0][0]; mo = red[1][0];
    #pragma unroll
    for (int i = 1; i < 8; i++) { ms = fmaxf(ms, red[0][i]); mo = fmaxf(mo, red[1][i]); }
    __syncthreads();

    float ss = 0.0f, so = 0.0f;
    #pragma unroll
    for (int j = 0; j < 8; j++) {
        s[j] = expf(s[j] - ms); ss += s[j];
        o[j] = expf(o[j] - mo); so += o[j];
    }
    #pragma unroll
    for (int off = 16; off; off >>= 1) {
        ss += __shfl_xor_sync(0xffffffffu, ss, off);
        so += __shfl_xor_sync(0xffffffffu, so, off);
    }
    if (ln == 0) { red[0][w] = ss; red[1][w] = so; }
    __syncthreads();
    ss = 0.0f; so = 0.0f;
    #pragma unroll
    for (int i = 0; i < 8; i++) { ss += red[0][i]; so += red[1][i]; }

    const float rs = 1.0f / ss, ro = 1.0f / so;
    #pragma unroll
    for (int j = 0; j < 8; j++) {
        int k = t + j * 256;
        float a = s[j] * rs;
        ps[k] = a;
        float comb = a + o[j] * ro;
        __nv_bfloat16 h = __float2bfloat16(comb);
        phr[k] = h;
        plr[k] = __float2bfloat16(comb - __bfloat162float(h));
    }
}

// ---------------- host ----------------------------------------------------------
extern "C" void kernel_launch(void* const* d_in, const int* in_sizes, int n_in,
                              void* d_out, int out_size)
{
    const float* x    = (const float*)d_in[0];
    const float* qin  = (const float*)d_in[1];
    const float* vin  = (const float*)d_in[2];
    const float* mask = (const float*)d_in[3];
    const float* Wk   = (const float*)d_in[4];
    const float* Wqs  = (const float*)d_in[5];
    const float* Wqo  = (const float*)d_in[6];
    const float* Wv   = (const float*)d_in[7];

    #define SYMP(T, p, s) T* p; { void* _t; cudaGetSymbolAddress(&_t, s); p = (T*)_t; }
    SYMP(__nv_bfloat16, xh,  g_xh)  SYMP(__nv_bfloat16, xl,  g_xl)
    SYMP(__nv_bfloat16, qih, g_qih) SYMP(__nv_bfloat16, qil, g_qil)
    SYMP(__nv_bfloat16, vih, g_vih) SYMP(__nv_bfloat16, vil, g_vil)
    SYMP(__nv_bfloat16, wkh, g_wkh) SYMP(__nv_bfloat16, wkl, g_wkl)
    SYMP(__nv_bfloat16, wqsh,g_wqsh)SYMP(__nv_bfloat16, wqsl,g_wqsl)
    SYMP(__nv_bfloat16, wqoh,g_wqoh)SYMP(__nv_bfloat16, wqol,g_wqol)
    SYMP(__nv_bfloat16, wvh, g_wvh) SYMP(__nv_bfloat16, wvl, g_wvl)
    SYMP(__nv_bfloat16, kh,  g_kh)  SYMP(__nv_bfloat16, kl,  g_kl)
    SYMP(__nv_bfloat16, qsh, g_qsh) SYMP(__nv_bfloat16, qsl, g_qsl)
    SYMP(__nv_bfloat16, qoh, g_qoh) SYMP(__nv_bfloat16, qol, g_qol)
    SYMP(__nv_bfloat16, vh,  g_vh)  SYMP(__nv_bfloat16, vl,  g_vl)
    SYMP(__nv_bfloat16, vth, g_vth) SYMP(__nv_bfloat16, vtl, g_vtl)
    SYMP(__nv_bfloat16, ph,  g_ph)  SYMP(__nv_bfloat16, pl,  g_pl)
    SYMP(float, po, g_po)

    float* out   = (float*)d_out;
    float* pself = out + ND;

    cudaFuncSetAttribute(gemm_ms<0>, cudaFuncAttributeMaxDynamicSharedMemorySize, GEMM_SMEM);
    cudaFuncSetAttribute(gemm_ms<1>, cudaFuncAttributeMaxDynamicSharedMemorySize, GEMM_SMEM);

    // 1) split inputs to bf16 hi/lo
    const int ND4 = (int)(ND / 4), NW4 = (int)(NW / 4);
    split_k<<<(ND4 + 255) / 256, 256>>>((const float4*)x,   (uint2*)xh,  (uint2*)xl,  ND4);
    split_k<<<(ND4 + 255) / 256, 256>>>((const float4*)qin, (uint2*)qih, (uint2*)qil, ND4);
    split_k<<<(ND4 + 255) / 256, 256>>>((const float4*)vin, (uint2*)vih, (uint2*)vil, ND4);
    split_k<<<(NW4 + 255) / 256, 256>>>((const float4*)Wk,  (uint2*)wkh, (uint2*)wkl, NW4);
    split_k<<<(NW4 + 255) / 256, 256>>>((const float4*)Wqs, (uint2*)wqsh,(uint2*)wqsl,NW4);
    split_k<<<(NW4 + 255) / 256, 256>>>((const float4*)Wqo, (uint2*)wqoh,(uint2*)wqol,NW4);
    split_k<<<(NW4 + 255) / 256, 256>>>((const float4*)Wv,  (uint2*)wvh, (uint2*)wvl, NW4);

    // 2) projections (NT, M=16384, N=1024, K=1024) -> bf16 split outputs
    dim3 gp(8, 64, 1), blk(256);
    gemm_ms<1><<<gp, blk, GEMM_SMEM>>>(xh,  xl,  wkh,  wkl,  nullptr, kh,  kl,  1024, 1024, 0, 0, 0);
    gemm_ms<1><<<gp, blk, GEMM_SMEM>>>(xh,  xl,  wqsh, wqsl, nullptr, qsh, qsl, 1024, 1024, 0, 0, 0);
    gemm_ms<1><<<gp, blk, GEMM_SMEM>>>(qih, qil, wqoh, wqol, nullptr, qoh, qol, 1024, 1024, 0, 0, 0);
    gemm_ms<1><<<gp, blk, GEMM_SMEM>>>(vih, vil, wvh,  wvl,  nullptr, vh,  vl,  1024, 1024, 0, 0, 0);

    // 3) transpose V per batch: [B,L,D] -> [B,D,L]
    dim3 gt(32, 64, 8), bt(32, 8);
    transp_k<<<gt, bt>>>(vh, vth);
    transp_k<<<gt, bt>>>(vl, vtl);

    // 4) scores (batched NT, M=N=2048, K=1024) -> fp32
    dim3 gs(16, 8, 8);
    gemm_ms<0><<<gs, blk, GEMM_SMEM>>>(qsh, qsl, kh, kl, pself, nullptr, nullptr,
                                       1024, 2048, (size_t)L_ * D_, (size_t)L_ * D_, (size_t)L_ * L_);
    gemm_ms<0><<<gs, blk, GEMM_SMEM>>>(qoh, qol, kh, kl, po, nullptr, nullptr,
                                       1024, 2048, (size_t)L_ * D_, (size_t)L_ * D_, (size_t)L_ * L_);

    // 5) dual softmax; emits p_self fp32 + combined-p bf16 split
    softmax_combine<<<B_ * L_, 256>>>(mask, pself, po, ph, pl);

    // 6) out = (p_self + p_other) @ V  (batched NT vs V^T, M=2048, N=1024, K=2048)
    dim3 gv(8, 8, 8);
    gemm_ms<0><<<gv, blk, GEMM_SMEM>>>(ph, pl, vth, vtl, out, nullptr, nullptr,
                                       2048, 1024, (size_t)L_ * L_, (size_t)D_ * L_, (size_t)L_ * D_);
}

// round 5
// speedup vs baseline: 2.9361x; 1.0580x over previous
#include <cuda_runtime.h>
#include <cuda_bf16.h>
#include <math.h>
#include <stdint.h>

#define B_ 8
#define L_ 2048
#define D_ 1024

static const size_t ND = (size_t)B_ * L_ * D_;   // 16,777,216
static const size_t NW = (size_t)D_ * D_;        // 1,048,576

// ---------------- device scratch (globals: no allocation APIs) ----------------
#define GBUF(name, n) __device__ __align__(256) __nv_bfloat16 name[n]
GBUF(g_xh, 16777216);  GBUF(g_xl, 16777216);
GBUF(g_qih, 16777216); GBUF(g_qil, 16777216);
GBUF(g_vih, 16777216); GBUF(g_vil, 16777216);
GBUF(g_wkh, 1048576);  GBUF(g_wkl, 1048576);
GBUF(g_wqsh, 1048576); GBUF(g_wqsl, 1048576);
GBUF(g_wqoh, 1048576); GBUF(g_wqol, 1048576);
GBUF(g_wvh, 1048576);  GBUF(g_wvl, 1048576);
GBUF(g_kh, 16777216);  GBUF(g_kl, 16777216);
GBUF(g_qsh, 16777216); GBUF(g_qsl, 16777216);
GBUF(g_qoh, 16777216); GBUF(g_qol, 16777216);
GBUF(g_vh, 16777216);  GBUF(g_vl, 16777216);
GBUF(g_vth, 16777216); GBUF(g_vtl, 16777216);
GBUF(g_ph, 33554432);  GBUF(g_pl, 33554432);
__device__ __align__(256) float g_po[33554432];

// ---------------- PTX helpers (base sm_103 target: NO tcgen05/TMA) ------------
__device__ __forceinline__ uint32_t smem_u32(const void* p) {
    uint32_t a;
    asm("{ .reg .u64 t; cvta.to.shared.u64 t, %1; cvt.u32.u64 %0, t; }" : "=r"(a) : "l"(p));
    return a;
}

#define CPASYNC(saddr, gptr) \
    asm volatile("cp.async.cg.shared.global [%0], [%1], 16;" \
                 :: "r"(saddr), "l"(gptr) : "memory")
#define CP_COMMIT() asm volatile("cp.async.commit_group;" ::: "memory")
#define CP_WAIT2()  asm volatile("cp.async.wait_group 2;" ::: "memory")

__device__ __forceinline__ void ldmx4(uint32_t* r, uint32_t addr) {
    asm volatile("ldmatrix.sync.aligned.m8n8.x4.shared.b16 {%0,%1,%2,%3}, [%4];"
                 : "=r"(r[0]), "=r"(r[1]), "=r"(r[2]), "=r"(r[3]) : "r"(addr));
}

__device__ __forceinline__ void mma16816(float* c, const uint32_t* a, const uint32_t* b) {
    asm volatile(
        "mma.sync.aligned.m16n8k16.row.col.f32.bf16.bf16.f32 "
        "{%0,%1,%2,%3}, {%4,%5,%6,%7}, {%8,%9}, {%0,%1,%2,%3};"
        : "+f"(c[0]), "+f"(c[1]), "+f"(c[2]), "+f"(c[3])
        : "r"(a[0]), "r"(a[1]), "r"(a[2]), "r"(a[3]), "r"(b[0]), "r"(b[1]));
}

// smem tile rows of 32 bf16 (64B, 4x16B chunks), XOR swizzle on chunk.
__device__ __forceinline__ uint32_t swz(int row, int chunk) {
    return (uint32_t)(row * 64 + (((chunk ^ ((row >> 1) & 3)) & 3) << 4));
}

// ---------------- pipelined bf16x3 warp-MMA GEMM body (NT) --------------------
// C[m,n] = sum_k (Ah+Al)[m,k]*(Bh+Bl)[n,k]   (Al*Bl dropped)
// CTA 256x128xK, Kstep=32, 4 stages, 8 warps (4m x 2n), warp tile 64x64.
// Stage layout: Ah[256x32]@0 (16KB), Al@16K, Bh[128x32]@32K (8KB), Bl@40K.
#define STG_BYTES 49152
#define GEMM_SMEM (4 * STG_BYTES)   // 192 KB

template <int EPI>
__device__ __forceinline__ void
gemm_body(const __nv_bfloat16* __restrict__ Ah, const __nv_bfloat16* __restrict__ Al,
          const __nv_bfloat16* __restrict__ Bh, const __nv_bfloat16* __restrict__ Bl,
          float* __restrict__ C, __nv_bfloat16* __restrict__ Ch, __nv_bfloat16* __restrict__ Cl,
          int K, int ldc, int m0, int n0)
{
    extern __shared__ __align__(128) char smem[];
    const uint32_t smemU = smem_u32(smem);

    const int tid  = threadIdx.x;
    const int wid  = tid >> 5;
    const int lane = tid & 31;

    const int wm64 = (wid & 3) * 64;
    const int wn64 = (wid >> 2) * 64;

    float acc[128];
    #pragma unroll
    for (int i = 0; i < 128; i++) acc[i] = 0.0f;

    const int KT = K >> 5;   // k-steps of 32

    // load mapping: A tensors 1024 chunks each (4/thread), B tensors 512 (2/thread)
    #define ISSUE_STAGE(KF, SLOT) do {                                        \
        uint32_t _sb = smemU + (uint32_t)(SLOT) * STG_BYTES;                  \
        size_t _ko = (size_t)(KF) * 32;                                       \
        _Pragma("unroll")                                                     \
        for (int _i = 0; _i < 4; _i++) {                                      \
            int _c = tid + _i * 256;                                          \
            int _r = _c >> 2, _ch = _c & 3;                                   \
            uint32_t _so = swz(_r, _ch);                                      \
            size_t _go = (size_t)(m0 + _r) * K + _ko + (size_t)_ch * 8;       \
            CPASYNC(_sb + _so,          Ah + _go);                            \
            CPASYNC(_sb + 16384u + _so, Al + _go);                            \
        }                                                                     \
        _Pragma("unroll")                                                     \
        for (int _i = 0; _i < 2; _i++) {                                      \
            int _c = tid + _i * 256;                                          \
            int _r = _c >> 2, _ch = _c & 3;                                   \
            uint32_t _so = swz(_r, _ch);                                      \
            size_t _go = (size_t)(n0 + _r) * K + _ko + (size_t)_ch * 8;       \
            CPASYNC(_sb + 32768u + _so, Bh + _go);                            \
            CPASYNC(_sb + 40960u + _so, Bl + _go);                            \
        }                                                                     \
    } while (0)

    // prologue: fill 3 stages
    ISSUE_STAGE(0, 0); CP_COMMIT();
    ISSUE_STAGE(1, 1); CP_COMMIT();
    ISSUE_STAGE(2, 2); CP_COMMIT();

    for (int kt = 0; kt < KT; kt++) {
        CP_WAIT2();
        __syncthreads();

        int kf = kt + 3;
        if (kf < KT) ISSUE_STAGE(kf, kf & 3);
        CP_COMMIT();

        const uint32_t sb = smemU + (uint32_t)(kt & 3) * STG_BYTES;
        #pragma unroll
        for (int k16 = 0; k16 < 2; k16++) {
            uint32_t bh[16], bl[16];
            #pragma unroll
            for (int tp = 0; tp < 4; tp++) {
                int brow = wn64 + tp * 16 + (lane & 7) + ((lane >> 4) << 3);
                int bch  = k16 * 2 + ((lane >> 3) & 1);
                uint32_t off = swz(brow, bch);
                ldmx4(&bh[tp * 4], sb + 32768u + off);
                ldmx4(&bl[tp * 4], sb + 40960u + off);
            }
            #pragma unroll
            for (int tm = 0; tm < 4; tm++) {
                int arow = wm64 + tm * 16 + (lane & 15);
                int ach  = k16 * 2 + (lane >> 4);
                uint32_t off = swz(arow, ach);
                uint32_t ah[4], al[4];
                ldmx4(ah, sb + off);
                ldmx4(al, sb + 16384u + off);
                #pragma unroll
                for (int tn = 0; tn < 8; tn++) {
                    float* c = acc + (tm * 8 + tn) * 4;
                    mma16816(c, ah, &bh[tn * 2]);
                    mma16816(c, al, &bh[tn * 2]);
                    mma16816(c, ah, &bl[tn * 2]);
                }
            }
        }
    }
    #undef ISSUE_STAGE

    // epilogue: direct stores from mma accumulator layout
    #pragma unroll
    for (int tm = 0; tm < 4; tm++) {
        #pragma unroll
        for (int tn = 0; tn < 8; tn++) {
            const float* c = acc + (tm * 8 + tn) * 4;
            int row0 = m0 + wm64 + tm * 16 + (lane >> 2);
            int col  = n0 + wn64 + tn * 8 + (lane & 3) * 2;
            size_t i0 = (size_t)row0 * ldc + col;
            size_t i1 = i0 + (size_t)8 * ldc;
            if (EPI == 0) {
                *(float2*)(C + i0) = make_float2(c[0], c[1]);
                *(float2*)(C + i1) = make_float2(c[2], c[3]);
            } else {
                #pragma unroll
                for (int p = 0; p < 2; p++) {
                    size_t ix = p ? i1 : i0;
                    float v0 = c[p * 2], v1 = c[p * 2 + 1];
                    __nv_bfloat16 h0 = __float2bfloat16(v0);
                    __nv_bfloat16 h1 = __float2bfloat16(v1);
                    __nv_bfloat16 l0 = __float2bfloat16(v0 - __bfloat162float(h0));
                    __nv_bfloat16 l1 = __float2bfloat16(v1 - __bfloat162float(h1));
                    uint32_t hp = (uint32_t)__bfloat16_as_ushort(h0) |
                                  ((uint32_t)__bfloat16_as_ushort(h1) << 16);
                    uint32_t lp = (uint32_t)__bfloat16_as_ushort(l0) |
                                  ((uint32_t)__bfloat16_as_ushort(l1) << 16);
                    *(uint32_t*)(Ch + ix) = hp;
                    *(uint32_t*)(Cl + ix) = lp;
                }
            }
        }
    }
}

// ---- merged projection GEMM: z selects one of 4 (A, W, C) tuples --------------
struct ProjP {
    const __nv_bfloat16 *Ah[4], *Al[4], *Bh[4], *Bl[4];
    __nv_bfloat16 *Ch[4], *Cl[4];
};
__global__ void __launch_bounds__(256, 1)
gemm_proj(ProjP p)
{
    const int g  = blockIdx.z;
    const int m0 = blockIdx.y * 256, n0 = blockIdx.x * 128;
    gemm_body<1>(p.Ah[g], p.Al[g], p.Bh[g], p.Bl[g],
                 nullptr, p.Ch[g], p.Cl[g], 1024, 1024, m0, n0);
}

// ---- merged score GEMMs: z = which*8 + batch -----------------------------------
struct ScoreP {
    const __nv_bfloat16 *Qh[2], *Ql[2];
    const __nv_bfloat16 *Kh, *Kl;
    float *C[2];
};
__global__ void __launch_bounds__(256, 1)
gemm_scores(ScoreP p)
{
    const int z = blockIdx.z;
    const int b = z & 7, w = z >> 3;
    const size_t offA = (size_t)b * L_ * D_;
    const int m0 = blockIdx.y * 256, n0 = blockIdx.x * 128;
    gemm_body<0>(p.Qh[w] + offA, p.Ql[w] + offA, p.Kh + offA, p.Kl + offA,
                 p.C[w] + (size_t)b * L_ * L_, nullptr, nullptr, 1024, 2048, m0, n0);
}

// ---- PV GEMM: z = batch ---------------------------------------------------------
__global__ void __launch_bounds__(256, 1)
gemm_pv(const __nv_bfloat16* __restrict__ Ah, const __nv_bfloat16* __restrict__ Al,
        const __nv_bfloat16* __restrict__ Bh, const __nv_bfloat16* __restrict__ Bl,
        float* __restrict__ C)
{
    const size_t z = blockIdx.z;
    const int m0 = blockIdx.y * 256, n0 = blockIdx.x * 128;
    gemm_body<0>(Ah + z * ((size_t)L_ * L_), Al + z * ((size_t)L_ * L_),
                 Bh + z * ((size_t)D_ * L_), Bl + z * ((size_t)D_ * L_),
                 C + z * ((size_t)L_ * D_), nullptr, nullptr, 2048, 1024, m0, n0);
}

// ---------------- fp32 -> bf16 hi/lo split, merged + grid-strided ---------------
struct SplitP { const float4* in[4]; uint2* hi[4]; uint2* lo[4]; };

__global__ void __launch_bounds__(256)
split_many(SplitP p, int n4)
{
    const int g = blockIdx.y;
    const float4* in = p.in[g];
    uint2* hi = p.hi[g];
    uint2* lo = p.lo[g];
    const int stride = gridDim.x * 256;
    for (int i = blockIdx.x * 256 + threadIdx.x; i < n4; i += stride) {
        float4 v = in[i];
        __nv_bfloat16 h0 = __float2bfloat16(v.x), h1 = __float2bfloat16(v.y);
        __nv_bfloat16 h2 = __float2bfloat16(v.z), h3 = __float2bfloat16(v.w);
        __nv_bfloat16 l0 = __float2bfloat16(v.x - __bfloat162float(h0));
        __nv_bfloat16 l1 = __float2bfloat16(v.y - __bfloat162float(h1));
        __nv_bfloat16 l2 = __float2bfloat16(v.z - __bfloat162float(h2));
        __nv_bfloat16 l3 = __float2bfloat16(v.w - __bfloat162float(h3));
        uint2 H, L;
        H.x = (uint32_t)__bfloat16_as_ushort(h0) | ((uint32_t)__bfloat16_as_ushort(h1) << 16);
        H.y = (uint32_t)__bfloat16_as_ushort(h2) | ((uint32_t)__bfloat16_as_ushort(h3) << 16);
        L.x = (uint32_t)__bfloat16_as_ushort(l0) | ((uint32_t)__bfloat16_as_ushort(l1) << 16);
        L.y = (uint32_t)__bfloat16_as_ushort(l2) | ((uint32_t)__bfloat16_as_ushort(l3) << 16);
        hi[i] = H; lo[i] = L;
    }
}

// ---------------- merged per-batch bf16 transpose: [B,L,D] -> [B,D,L] ----------
__global__ void __launch_bounds__(256)
transp_k2(const __nv_bfloat16* __restrict__ s0, __nv_bfloat16* __restrict__ d0,
          const __nv_bfloat16* __restrict__ s1, __nv_bfloat16* __restrict__ d1)
{
    __shared__ __nv_bfloat16 t[32][33];
    const int z = blockIdx.z;
    const int b = z & 7, w = z >> 3;
    const __nv_bfloat16* src = (w ? s1 : s0) + (size_t)b * L_ * D_;
    __nv_bfloat16* dst = (w ? d1 : d0) + (size_t)b * D_ * L_;
    const int dd0 = blockIdx.x * 32, l0 = blockIdx.y * 32;
    const int tx = threadIdx.x, ty = threadIdx.y;  // 32 x 8
    #pragma unroll
    for (int j = 0; j < 4; j++)
        t[ty + j * 8][tx] = src[(size_t)(l0 + ty + j * 8) * D_ + dd0 + tx];
    __syncthreads();
    #pragma unroll
    for (int j = 0; j < 4; j++)
        dst[(size_t)(dd0 + ty + j * 8) * L_ + l0 + tx] = t[tx][ty + j * 8];
}

// ---------------- dual softmax + combined-p bf16 split --------------------------
__global__ void __launch_bounds__(256)
softmax_combine(const float* __restrict__ mask,
                float* __restrict__ psf,          // raw self scores -> p_self (fp32 out)
                const float* __restrict__ po,     // raw other scores
                __nv_bfloat16* __restrict__ ph,   // (p_self+p_other) hi
                __nv_bfloat16* __restrict__ pl)   // (p_self+p_other) lo
{
    const int row = blockIdx.x;
    const int b   = row >> 11;
    float* ps = psf + (size_t)row * L_;
    const float* pc = po + (size_t)row * L_;
    __nv_bfloat16* phr = ph + (size_t)row * L_;
    __nv_bfloat16* plr = pl + (size_t)row * L_;
    const float* mk = mask + (size_t)b * L_;

    const int t = threadIdx.x;
    const float scale = 0.03125f;

    float s[8], o[8];
    #pragma unroll
    for (int j = 0; j < 8; j++) {
        int k = t + j * 256;
        float pen = (1.0f - mk[k]) * -100000.0f;
        s[j] = ps[k] * scale + pen;
        o[j] = pc[k] * scale + pen;
    }

    __shared__ float red[2][8];
    const int w = t >> 5, ln = t & 31;

    float ms = -INFINITY, mo = -INFINITY;
    #pragma unroll
    for (int j = 0; j < 8; j++) { ms = fmaxf(ms, s[j]); mo = fmaxf(mo, o[j]); }
    #pragma unroll
    for (int off = 16; off; off >>= 1) {
        ms = fmaxf(ms, __shfl_xor_sync(0xffffffffu, ms, off));
        mo = fmaxf(mo, __shfl_xor_sync(0xffffffffu, mo, off));
    }
    if (ln == 0) { red[0][w] = ms; red[1][w] = mo; }
    __syncthreads();
    ms = red[0][0]; mo = red[1][0];
    #pragma unroll
    for (int i = 1; i < 8; i++) { ms = fmaxf(ms, red[0][i]); mo = fmaxf(mo, red[1][i]); }
    __syncthreads();

    float ss = 0.0f, so = 0.0f;
    #pragma unroll
    for (int j = 0; j < 8; j++) {
        s[j] = expf(s[j] - ms); ss += s[j];
        o[j] = expf(o[j] - mo); so += o[j];
    }
    #pragma unroll
    for (int off = 16; off; off >>= 1) {
        ss += __shfl_xor_sync(0xffffffffu, ss, off);
        so += __shfl_xor_sync(0xffffffffu, so, off);
    }
    if (ln == 0) { red[0][w] = ss; red[1][w] = so; }
    __syncthreads();
    ss = 0.0f; so = 0.0f;
    #pragma unroll
    for (int i = 0; i < 8; i++) { ss += red[0][i]; so += red[1][i]; }

    const float rs = 1.0f / ss, ro = 1.0f / so;
    #pragma unroll
    for (int j = 0; j < 8; j++) {
        int k = t + j * 256;
        float a = s[j] * rs;
        ps[k] = a;
        float comb = a + o[j] * ro;
        __nv_bfloat16 h = __float2bfloat16(comb);
        phr[k] = h;
        plr[k] = __float2bfloat16(comb - __bfloat162float(h));
    }
}

// ---------------- host ----------------------------------------------------------
extern "C" void kernel_launch(void* const* d_in, const int* in_sizes, int n_in,
                              void* d_out, int out_size)
{
    const float* x    = (const float*)d_in[0];
    const float* qin  = (const float*)d_in[1];
    const float* vin  = (const float*)d_in[2];
    const float* mask = (const float*)d_in[3];
    const float* Wk   = (const float*)d_in[4];
    const float* Wqs  = (const float*)d_in[5];
    const float* Wqo  = (const float*)d_in[6];
    const float* Wv   = (const float*)d_in[7];

    #define SYMP(T, p, s) T* p; { void* _t; cudaGetSymbolAddress(&_t, s); p = (T*)_t; }
    SYMP(__nv_bfloat16, xh,  g_xh)  SYMP(__nv_bfloat16, xl,  g_xl)
    SYMP(__nv_bfloat16, qih, g_qih) SYMP(__nv_bfloat16, qil, g_qil)
    SYMP(__nv_bfloat16, vih, g_vih) SYMP(__nv_bfloat16, vil, g_vil)
    SYMP(__nv_bfloat16, wkh, g_wkh) SYMP(__nv_bfloat16, wkl, g_wkl)
    SYMP(__nv_bfloat16, wqsh,g_wqsh)SYMP(__nv_bfloat16, wqsl,g_wqsl)
    SYMP(__nv_bfloat16, wqoh,g_wqoh)SYMP(__nv_bfloat16, wqol,g_wqol)
    SYMP(__nv_bfloat16, wvh, g_wvh) SYMP(__nv_bfloat16, wvl, g_wvl)
    SYMP(__nv_bfloat16, kh,  g_kh)  SYMP(__nv_bfloat16, kl,  g_kl)
    SYMP(__nv_bfloat16, qsh, g_qsh) SYMP(__nv_bfloat16, qsl, g_qsl)
    SYMP(__nv_bfloat16, qoh, g_qoh) SYMP(__nv_bfloat16, qol, g_qol)
    SYMP(__nv_bfloat16, vh,  g_vh)  SYMP(__nv_bfloat16, vl,  g_vl)
    SYMP(__nv_bfloat16, vth, g_vth) SYMP(__nv_bfloat16, vtl, g_vtl)
    SYMP(__nv_bfloat16, ph,  g_ph)  SYMP(__nv_bfloat16, pl,  g_pl)
    SYMP(float, po, g_po)

    float* out   = (float*)d_out;
    float* pself = out + ND;

    cudaFuncSetAttribute(gemm_proj,   cudaFuncAttributeMaxDynamicSharedMemorySize, GEMM_SMEM);
    cudaFuncSetAttribute(gemm_scores, cudaFuncAttributeMaxDynamicSharedMemorySize, GEMM_SMEM);
    cudaFuncSetAttribute(gemm_pv,     cudaFuncAttributeMaxDynamicSharedMemorySize, GEMM_SMEM);

    // 1) split inputs to bf16 hi/lo (merged, grid-strided)
    const int ND4 = (int)(ND / 4), NW4 = (int)(NW / 4);
    {
        SplitP sp;
        sp.in[0] = (const float4*)x;   sp.hi[0] = (uint2*)xh;  sp.lo[0] = (uint2*)xl;
        sp.in[1] = (const float4*)qin; sp.hi[1] = (uint2*)qih; sp.lo[1] = (uint2*)qil;
        sp.in[2] = (const float4*)vin; sp.hi[2] = (uint2*)vih; sp.lo[2] = (uint2*)vil;
        sp.in[3] = sp.in[0]; sp.hi[3] = sp.hi[0]; sp.lo[3] = sp.lo[0]; // unused
        split_many<<<dim3(1184, 3), 256>>>(sp, ND4);

        SplitP sw;
        sw.in[0] = (const float4*)Wk;  sw.hi[0] = (uint2*)wkh;  sw.lo[0] = (uint2*)wkl;
        sw.in[1] = (const float4*)Wqs; sw.hi[1] = (uint2*)wqsh; sw.lo[1] = (uint2*)wqsl;
        sw.in[2] = (const float4*)Wqo; sw.hi[2] = (uint2*)wqoh; sw.lo[2] = (uint2*)wqol;
        sw.in[3] = (const float4*)Wv;  sw.hi[3] = (uint2*)wvh;  sw.lo[3] = (uint2*)wvl;
        split_many<<<dim3(296, 4), 256>>>(sw, NW4);
    }

    // 2) projections merged into ONE launch (z selects GEMM), M=16384,N=1024,K=1024
    {
        ProjP pp;
        pp.Ah[0] = xh;  pp.Al[0] = xl;  pp.Bh[0] = wkh;  pp.Bl[0] = wkl;  pp.Ch[0] = kh;  pp.Cl[0] = kl;
        pp.Ah[1] = xh;  pp.Al[1] = xl;  pp.Bh[1] = wqsh; pp.Bl[1] = wqsl; pp.Ch[1] = qsh; pp.Cl[1] = qsl;
        pp.Ah[2] = qih; pp.Al[2] = qil; pp.Bh[2] = wqoh; pp.Bl[2] = wqol; pp.Ch[2] = qoh; pp.Cl[2] = qol;
        pp.Ah[3] = vih; pp.Al[3] = vil; pp.Bh[3] = wvh;  pp.Bl[3] = wvl;  pp.Ch[3] = vh;  pp.Cl[3] = vl;
        gemm_proj<<<dim3(8, 64, 4), 256, GEMM_SMEM>>>(pp);
    }

    // 3) transpose V per batch (both hi/lo in one launch): [B,L,D] -> [B,D,L]
    transp_k2<<<dim3(32, 64, 16), dim3(32, 8)>>>(vh, vth, vl, vtl);

    // 4) scores merged into ONE launch (z = which*8 + batch), M=N=2048, K=1024
    {
        ScoreP sc;
        sc.Qh[0] = qsh; sc.Ql[0] = qsl; sc.C[0] = pself;
        sc.Qh[1] = qoh; sc.Ql[1] = qol; sc.C[1] = po;
        sc.Kh = kh; sc.Kl = kl;
        gemm_scores<<<dim3(16, 8, 16), 256, GEMM_SMEM>>>(sc);
    }

    // 5) dual softmax; emits p_self fp32 + combined-p bf16 split
    softmax_combine<<<B_ * L_, 256>>>(mask, pself, po, ph, pl);

    // 6) out = (p_self + p_other) @ V  (batched NT vs V^T, M=2048, N=1024, K=2048)
    gemm_pv<<<dim3(8, 8, 8), 256, GEMM_SMEM>>>(ph, pl, vth, vtl, out);
}